// round 1
// baseline (speedup 1.0000x reference)
#include <cuda_runtime.h>
#include <math.h>

#define NC 20000

// slot-major accumulators: [slot*NC + c]
// slots: 0..2 = Sx,Sy,Sz ; 3..8 = Sxx,Sxy,Sxz,Syy,Syz,Szz ; 9 = count
__device__ float g_acc[10 * NC];
__device__ float g_sc[NC];
__device__ float g_cen[3 * NC];
__device__ float g_v0[3 * NC];
__device__ float g_dirwt[NC];

__global__ void k_zero() {
    int i = blockIdx.x * blockDim.x + threadIdx.x;
    if (i < 10 * NC) g_acc[i] = 0.0f;
    if (i < NC) g_sc[i] = 0.0f;
}

__global__ void k_accum(const float* __restrict__ data,
                        const int* __restrict__ cl, int n) {
    int i = blockIdx.x * blockDim.x + threadIdx.x;
    if (i >= n) return;
    const float2* d2 = reinterpret_cast<const float2*>(data);
    float2 xy = __ldg(&d2[3 * i]);       // x, y
    float2 zw = __ldg(&d2[3 * i + 1]);   // z, (unused)
    float x = xy.x, y = xy.y, z = zw.x;
    int c = __ldg(&cl[i]);
    atomicAdd(&g_acc[0 * NC + c], x);
    atomicAdd(&g_acc[1 * NC + c], y);
    atomicAdd(&g_acc[2 * NC + c], z);
    atomicAdd(&g_acc[3 * NC + c], x * x);
    atomicAdd(&g_acc[4 * NC + c], x * y);
    atomicAdd(&g_acc[5 * NC + c], x * z);
    atomicAdd(&g_acc[6 * NC + c], y * y);
    atomicAdd(&g_acc[7 * NC + c], y * z);
    atomicAdd(&g_acc[8 * NC + c], z * z);
    atomicAdd(&g_acc[9 * NC + c], 1.0f);
}

__global__ void k_cluster(float* __restrict__ out) {
    int c = blockIdx.x * blockDim.x + threadIdx.x;
    if (c >= NC) return;

    double n  = (double)g_acc[9 * NC + c];
    double Sx = (double)g_acc[0 * NC + c];
    double Sy = (double)g_acc[1 * NC + c];
    double Sz = (double)g_acc[2 * NC + c];
    double inv = 1.0 / n;
    double cx = Sx * inv, cy = Sy * inv, cz = Sz * inv;

    // A = Sum xx^T - n * c c^T  (= Sxx - Sx*c etc.)
    double a00 = (double)g_acc[3 * NC + c] - Sx * cx;
    double a01 = (double)g_acc[4 * NC + c] - Sx * cy;
    double a02 = (double)g_acc[5 * NC + c] - Sx * cz;
    double a11 = (double)g_acc[6 * NC + c] - Sy * cy;
    double a12 = (double)g_acc[7 * NC + c] - Sy * cz;
    double a22 = (double)g_acc[8 * NC + c] - Sz * cz;

    // closed-form symmetric 3x3 eigenvalues (ascending e3 <= e2 <= e1)
    double q = (a00 + a11 + a22) / 3.0;
    double b00 = a00 - q, b11 = a11 - q, b22 = a22 - q;
    double p2 = b00 * b00 + b11 * b11 + b22 * b22
              + 2.0 * (a01 * a01 + a02 * a02 + a12 * a12);
    double p = sqrt(p2 / 6.0);

    double e1 = q, e2 = q, e3 = q;
    double vx = 1.0, vy = 0.0, vz = 0.0;

    if (p > 0.0) {
        double ip = 1.0 / p;
        double c00 = b00 * ip, c11 = b11 * ip, c22 = b22 * ip;
        double c01 = a01 * ip, c02 = a02 * ip, c12 = a12 * ip;
        double r = 0.5 * (c00 * (c11 * c22 - c12 * c12)
                        - c01 * (c01 * c22 - c12 * c02)
                        + c02 * (c01 * c12 - c11 * c02));
        r = fmin(1.0, fmax(-1.0, r));
        double phi = acos(r) / 3.0;
        e1 = q + 2.0 * p * cos(phi);                         // largest
        e3 = q + 2.0 * p * cos(phi + 2.0943951023931953);    // smallest
        e2 = 3.0 * q - e1 - e3;                              // middle

        // eigenvector of e1 via projector M = (A - e2 I)(A - e3 I):
        // M = (e1-e2)(e1-e3) v v^T, take largest-norm column.
        double p00 = a00 - e2, p11 = a11 - e2, p22 = a22 - e2;
        double q00 = a00 - e3, q11 = a11 - e3, q22 = a22 - e3;

        // column 0 of (A - e3 I): (q00, a01, a02)
        double m0x = p00 * q00 + a01 * a01 + a02 * a02;
        double m0y = a01 * q00 + p11 * a01 + a12 * a02;
        double m0z = a02 * q00 + a12 * a01 + p22 * a02;
        // column 1: (a01, q11, a12)
        double m1x = p00 * a01 + a01 * q11 + a02 * a12;
        double m1y = a01 * a01 + p11 * q11 + a12 * a12;
        double m1z = a02 * a01 + a12 * q11 + p22 * a12;
        // column 2: (a02, a12, q22)
        double m2x = p00 * a02 + a01 * a12 + a02 * q22;
        double m2y = a01 * a02 + p11 * a12 + a12 * q22;
        double m2z = a02 * a02 + a12 * a12 + p22 * q22;

        double n0 = m0x * m0x + m0y * m0y + m0z * m0z;
        double n1 = m1x * m1x + m1y * m1y + m1z * m1z;
        double n2 = m2x * m2x + m2y * m2y + m2z * m2z;

        if (n0 >= n1 && n0 >= n2) { vx = m0x; vy = m0y; vz = m0z; }
        else if (n1 >= n2)        { vx = m1x; vy = m1y; vz = m1z; }
        else                      { vx = m2x; vy = m2y; vz = m2z; }

        double nv = vx * vx + vy * vy + vz * vz;
        if (nv > 0.0) {
            double s = 1.0 / sqrt(nv);
            vx *= s; vy *= s; vz *= s;
        } else {
            vx = 1.0; vy = 0.0; vz = 0.0;
        }
    }

    float* o = out + (size_t)c * 16;
    o[0] = (float)cx; o[1] = (float)cy; o[2] = (float)cz;
    double iw = 1.0 / e1;
    o[3]  = (float)(a00 * iw); o[4]  = (float)(a01 * iw); o[5]  = (float)(a02 * iw);
    o[6]  = (float)(a01 * iw); o[7]  = (float)(a11 * iw); o[8]  = (float)(a12 * iw);
    o[9]  = (float)(a02 * iw); o[10] = (float)(a12 * iw); o[11] = (float)(a22 * iw);
    o[15] = (float)n;

    g_cen[3 * c + 0] = (float)cx;
    g_cen[3 * c + 1] = (float)cy;
    g_cen[3 * c + 2] = (float)cz;
    g_v0[3 * c + 0] = (float)vx;
    g_v0[3 * c + 1] = (float)vy;
    g_v0[3 * c + 2] = (float)vz;
    g_dirwt[c] = (float)(1.0 - e2 / e1);
}

__global__ void k_sc(const float* __restrict__ data,
                     const int* __restrict__ cl, int n) {
    int i = blockIdx.x * blockDim.x + threadIdx.x;
    if (i >= n) return;
    const float2* d2 = reinterpret_cast<const float2*>(data);
    float2 xy = __ldg(&d2[3 * i]);
    float2 zw = __ldg(&d2[3 * i + 1]);
    int c = __ldg(&cl[i]);
    float xc = xy.x - g_cen[3 * c + 0];
    float yc = xy.y - g_cen[3 * c + 1];
    float zc = zw.x - g_cen[3 * c + 2];
    float vx = g_v0[3 * c + 0];
    float vy = g_v0[3 * c + 1];
    float vz = g_v0[3 * c + 2];
    float x0 = xc * vx + yc * vy + zc * vz;
    float px = xc - x0 * vx;
    float py = yc - x0 * vy;
    float pz = zc - x0 * vz;
    float np0 = sqrtf(px * px + py * py + pz * pz);
    atomicAdd(&g_sc[c], x0 * np0);
}

__global__ void k_final(float* __restrict__ out) {
    int c = blockIdx.x * blockDim.x + threadIdx.x;
    if (c >= NC) return;
    float s = g_sc[c];
    float d = g_dirwt[c];
    float f = (s < 0.0f) ? -d : d;
    float* o = out + (size_t)c * 16;
    o[12] = g_v0[3 * c + 0] * f;
    o[13] = g_v0[3 * c + 1] * f;
    o[14] = g_v0[3 * c + 2] * f;
}

extern "C" void kernel_launch(void* const* d_in, const int* in_sizes, int n_in,
                              void* d_out, int out_size) {
    const float* data = (const float*)d_in[0];
    const int* cl = (const int*)d_in[1];
    float* out = (float*)d_out;
    int n = in_sizes[1];  // number of voxels (clusts element count)

    k_zero<<<(10 * NC + 255) / 256, 256>>>();
    k_accum<<<(n + 255) / 256, 256>>>(data, cl, n);
    k_cluster<<<(NC + 255) / 256, 256>>>(out);
    k_sc<<<(n + 255) / 256, 256>>>(data, cl, n);
    k_final<<<(NC + 255) / 256, 256>>>(out);
}

// round 2
// speedup vs baseline: 1.6854x; 1.6854x over previous
#include <cuda_runtime.h>
#include <math.h>

#define NC 20000
#define IPT 4

// cluster-major accumulators: 12 floats per cluster, 16B aligned.
// [0..3] = Sx,Sy,Sz,count   [4..7] = Sxx,Sxy,Sxz,Syy   [8..9] = Syz,Szz
__device__ __align__(16) float g_acc[12 * NC];
__device__ float g_sc[NC];
// per-cluster params: [2c] = (cx,cy,cz,_), [2c+1] = (vx,vy,vz,dirwt)
__device__ __align__(16) float4 g_cp[2 * NC];

__global__ void k_zero() {
    int i = blockIdx.x * blockDim.x + threadIdx.x;
    if (i < 12 * NC) g_acc[i] = 0.0f;
    if (i < NC) g_sc[i] = 0.0f;
}

__device__ __forceinline__ void red4(float* p, float a, float b, float c, float d) {
    asm volatile("red.global.add.v4.f32 [%0], {%1,%2,%3,%4};"
                 :: "l"(p), "f"(a), "f"(b), "f"(c), "f"(d) : "memory");
}
__device__ __forceinline__ void red2(float* p, float a, float b) {
    asm volatile("red.global.add.v2.f32 [%0], {%1,%2};"
                 :: "l"(p), "f"(a), "f"(b) : "memory");
}

__global__ void k_accum(const float* __restrict__ data,
                        const int* __restrict__ cl, int n) {
    int i = blockIdx.x * blockDim.x + threadIdx.x;
    if (i >= n) return;
    const float2* d2 = reinterpret_cast<const float2*>(data);
    float2 xy = __ldcs(&d2[3 * i]);       // x, y
    float2 zw = __ldcs(&d2[3 * i + 1]);   // z, (unused)
    float x = xy.x, y = xy.y, z = zw.x;
    int c = __ldg(&cl[i]);
    float* base = &g_acc[c * 12];
    red4(base,     x,     y,     z,     1.0f);
    red4(base + 4, x * x, x * y, x * z, y * y);
    red2(base + 8, y * z, z * z);
}

__global__ void k_cluster(float* __restrict__ out) {
    int c = blockIdx.x * blockDim.x + threadIdx.x;
    if (c >= NC) return;
    const float* b = &g_acc[c * 12];

    double Sx = (double)b[0], Sy = (double)b[1], Sz = (double)b[2];
    double n  = (double)b[3];
    double inv = 1.0 / n;
    double cx = Sx * inv, cy = Sy * inv, cz = Sz * inv;

    double a00 = (double)b[4] - Sx * cx;
    double a01 = (double)b[5] - Sx * cy;
    double a02 = (double)b[6] - Sx * cz;
    double a11 = (double)b[7] - Sy * cy;
    double a12 = (double)b[8] - Sy * cz;
    double a22 = (double)b[9] - Sz * cz;

    // closed-form symmetric 3x3 eigenvalues (e3 <= e2 <= e1)
    double q = (a00 + a11 + a22) / 3.0;
    double b00 = a00 - q, b11 = a11 - q, b22 = a22 - q;
    double p2 = b00 * b00 + b11 * b11 + b22 * b22
              + 2.0 * (a01 * a01 + a02 * a02 + a12 * a12);
    double p = sqrt(p2 / 6.0);

    double e1 = q, e2 = q;
    double vx = 1.0, vy = 0.0, vz = 0.0;

    if (p > 0.0) {
        double ip = 1.0 / p;
        double c00 = b00 * ip, c11 = b11 * ip, c22 = b22 * ip;
        double c01 = a01 * ip, c02 = a02 * ip, c12 = a12 * ip;
        double r = 0.5 * (c00 * (c11 * c22 - c12 * c12)
                        - c01 * (c01 * c22 - c12 * c02)
                        + c02 * (c01 * c12 - c11 * c02));
        r = fmin(1.0, fmax(-1.0, r));
        double phi = acos(r) / 3.0;
        e1 = q + 2.0 * p * cos(phi);
        double e3 = q + 2.0 * p * cos(phi + 2.0943951023931953);
        e2 = 3.0 * q - e1 - e3;

        // eigenvector of e1 via projector M = (A - e2 I)(A - e3 I)
        double p00 = a00 - e2, p11 = a11 - e2, p22 = a22 - e2;
        double q00 = a00 - e3, q11 = a11 - e3, q22 = a22 - e3;

        double m0x = p00 * q00 + a01 * a01 + a02 * a02;
        double m0y = a01 * q00 + p11 * a01 + a12 * a02;
        double m0z = a02 * q00 + a12 * a01 + p22 * a02;
        double m1x = p00 * a01 + a01 * q11 + a02 * a12;
        double m1y = a01 * a01 + p11 * q11 + a12 * a12;
        double m1z = a02 * a01 + a12 * q11 + p22 * a12;
        double m2x = p00 * a02 + a01 * a12 + a02 * q22;
        double m2y = a01 * a02 + p11 * a12 + a12 * q22;
        double m2z = a02 * a02 + a12 * a12 + p22 * q22;

        double n0 = m0x * m0x + m0y * m0y + m0z * m0z;
        double n1 = m1x * m1x + m1y * m1y + m1z * m1z;
        double n2 = m2x * m2x + m2y * m2y + m2z * m2z;

        if (n0 >= n1 && n0 >= n2) { vx = m0x; vy = m0y; vz = m0z; }
        else if (n1 >= n2)        { vx = m1x; vy = m1y; vz = m1z; }
        else                      { vx = m2x; vy = m2y; vz = m2z; }

        double nv = vx * vx + vy * vy + vz * vz;
        if (nv > 0.0) {
            double s = 1.0 / sqrt(nv);
            vx *= s; vy *= s; vz *= s;
        } else { vx = 1.0; vy = 0.0; vz = 0.0; }
    }

    float* o = out + (size_t)c * 16;
    o[0] = (float)cx; o[1] = (float)cy; o[2] = (float)cz;
    double iw = 1.0 / e1;
    o[3]  = (float)(a00 * iw); o[4]  = (float)(a01 * iw); o[5]  = (float)(a02 * iw);
    o[6]  = (float)(a01 * iw); o[7]  = (float)(a11 * iw); o[8]  = (float)(a12 * iw);
    o[9]  = (float)(a02 * iw); o[10] = (float)(a12 * iw); o[11] = (float)(a22 * iw);
    o[15] = (float)n;

    g_cp[2 * c]     = make_float4((float)cx, (float)cy, (float)cz, 0.0f);
    g_cp[2 * c + 1] = make_float4((float)vx, (float)vy, (float)vz,
                                  (float)(1.0 - e2 / e1));
}

__global__ void k_sc(const float* __restrict__ data,
                     const int* __restrict__ cl, int n) {
    int base = blockIdx.x * blockDim.x * IPT + threadIdx.x;
    const float2* d2 = reinterpret_cast<const float2*>(data);

    float x[IPT], y[IPT], z[IPT];
    int c[IPT];
    bool ok[IPT];

    #pragma unroll
    for (int j = 0; j < IPT; j++) {
        int i = base + j * blockDim.x;
        ok[j] = (i < n);
        if (ok[j]) {
            float2 xy = __ldcs(&d2[3 * i]);
            float2 zw = __ldcs(&d2[3 * i + 1]);
            c[j] = __ldg(&cl[i]);
            x[j] = xy.x; y[j] = xy.y; z[j] = zw.x;
        }
    }

    float4 cen[IPT], v0[IPT];
    #pragma unroll
    for (int j = 0; j < IPT; j++) {
        if (ok[j]) {
            cen[j] = g_cp[2 * c[j]];
            v0[j]  = g_cp[2 * c[j] + 1];
        }
    }

    #pragma unroll
    for (int j = 0; j < IPT; j++) {
        if (ok[j]) {
            float xc = x[j] - cen[j].x;
            float yc = y[j] - cen[j].y;
            float zc = z[j] - cen[j].z;
            float vx = v0[j].x, vy = v0[j].y, vz = v0[j].z;
            float x0 = xc * vx + yc * vy + zc * vz;
            float px = xc - x0 * vx;
            float py = yc - x0 * vy;
            float pz = zc - x0 * vz;
            float np0 = sqrtf(px * px + py * py + pz * pz);
            atomicAdd(&g_sc[c[j]], x0 * np0);
        }
    }
}

__global__ void k_final(float* __restrict__ out) {
    int c = blockIdx.x * blockDim.x + threadIdx.x;
    if (c >= NC) return;
    float s = g_sc[c];
    float4 v = g_cp[2 * c + 1];
    float f = (s < 0.0f) ? -v.w : v.w;
    float* o = out + (size_t)c * 16;
    o[12] = v.x * f;
    o[13] = v.y * f;
    o[14] = v.z * f;
}

extern "C" void kernel_launch(void* const* d_in, const int* in_sizes, int n_in,
                              void* d_out, int out_size) {
    const float* data = (const float*)d_in[0];
    const int* cl = (const int*)d_in[1];
    float* out = (float*)d_out;
    int n = in_sizes[1];

    k_zero<<<(12 * NC + 255) / 256, 256>>>();
    k_accum<<<(n + 255) / 256, 256>>>(data, cl, n);
    k_cluster<<<(NC + 255) / 256, 256>>>(out);
    k_sc<<<(n + 256 * IPT - 1) / (256 * IPT), 256>>>(data, cl, n);
    k_final<<<(NC + 255) / 256, 256>>>(out);
}